// round 11
// baseline (speedup 1.0000x reference)
#include <cuda_runtime.h>
#include <stdint.h>

#define CLUSTER_N 8
#define CLUSTER_THREADS 512
#define NUM_CLUSTERS 18   // 18*8 = 144 CTAs, one per SM (148-SM chip)

// ---------------- bias init (vectorized) ----------------
__global__ void bias_init_kernel(const float* __restrict__ Param_b,
                                 const int4* __restrict__ b_params4,
                                 float4* __restrict__ out4, int n4) {
    int i = blockIdx.x * blockDim.x + threadIdx.x;
    if (i < n4) {
        int4 b = __ldcs(&b_params4[i]);
        float4 v;
        v.x = __ldg(&Param_b[b.x]);
        v.y = __ldg(&Param_b[b.y]);
        v.z = __ldg(&Param_b[b.z]);
        v.w = __ldg(&Param_b[b.w]);
        out4[i] = v;
    }
}

__global__ void bias_init_tail_kernel(const float* __restrict__ Param_b,
                                      const int* __restrict__ b_params,
                                      float* __restrict__ out, int start, int n) {
    int i = start + blockIdx.x * blockDim.x + threadIdx.x;
    if (i < n) out[i] = Param_b[b_params[i]];
}

// ---------------- DSMEM helpers ----------------
__device__ __forceinline__ uint32_t smem_u32(const void* p) {
    uint32_t a;
    asm("{ .reg .u64 t; cvta.to.shared.u64 t, %1; cvt.u32.u64 %0, t; }"
        : "=r"(a) : "l"(p));
    return a;
}

// Gather x[c] from the owning CTA's shared-memory slice via the cluster
// interconnect (bypasses L1tex/L2 entirely).
__device__ __forceinline__ float cluster_gather(uint32_t sbase, int c,
                                                int shift, int mask) {
    uint32_t owner = ((uint32_t)c) >> shift;
    uint32_t local = sbase + (((uint32_t)c & (uint32_t)mask) << 2);
    uint32_t remote;
    asm("mapa.shared::cluster.u32 %0, %1, %2;"
        : "=r"(remote) : "r"(local), "r"(owner));
    float v;
    asm volatile("ld.shared::cluster.f32 %0, [%1];" : "=f"(v) : "r"(remote));
    return v;
}

// ---------------- cluster scatter kernel ----------------
// x fully resident in distributed shared memory across an 8-CTA cluster.
// Index streams stream from DRAM (__ldcs); atomics go to global out (L2).
// Grid-stride loop manually unrolled x4 to keep 12 index loads + 16 remote
// gathers in flight per thread (front-batched MLP).
__global__ void __launch_bounds__(CLUSTER_THREADS, 1) edge_scatter_cluster(
        const float* __restrict__ x,
        const float* __restrict__ Param_W,
        const int4* __restrict__ w_rows4,
        const int4* __restrict__ w_cols4,
        const int4* __restrict__ w_params4,
        float* __restrict__ out, int e4,
        int slice, int shift, int mask) {
    extern __shared__ float s_x[];

    // load this CTA's x slice (coalesced float4)
    uint32_t rank;
    asm("mov.u32 %0, %%cluster_ctarank;" : "=r"(rank));
    {
        const float4* xs = (const float4*)(x + (size_t)rank * slice);
        float4* s4 = (float4*)s_x;
        int nf4 = slice >> 2;
        for (int i = threadIdx.x; i < nf4; i += blockDim.x)
            s4[i] = xs[i];
    }
    uint32_t sbase = smem_u32(s_x);

    asm volatile("barrier.cluster.arrive.aligned;" ::: "memory");
    asm volatile("barrier.cluster.wait.aligned;" ::: "memory");

    int tid = blockIdx.x * blockDim.x + threadIdx.x;
    int stride = gridDim.x * blockDim.x;

    int i = tid;
    // ---- unrolled-by-4 main loop ----
    for (; i + 3 * stride < e4; i += 4 * stride) {
        int i0 = i, i1 = i + stride, i2 = i + 2 * stride, i3 = i + 3 * stride;

        int4 r0 = __ldcs(&w_rows4[i0]);
        int4 c0 = __ldcs(&w_cols4[i0]);
        int4 p0 = __ldcs(&w_params4[i0]);
        int4 r1 = __ldcs(&w_rows4[i1]);
        int4 c1 = __ldcs(&w_cols4[i1]);
        int4 p1 = __ldcs(&w_params4[i1]);
        int4 r2 = __ldcs(&w_rows4[i2]);
        int4 c2 = __ldcs(&w_cols4[i2]);
        int4 p2 = __ldcs(&w_params4[i2]);
        int4 r3 = __ldcs(&w_rows4[i3]);
        int4 c3 = __ldcs(&w_cols4[i3]);
        int4 p3 = __ldcs(&w_params4[i3]);

        float x00 = cluster_gather(sbase, c0.x, shift, mask);
        float x01 = cluster_gather(sbase, c0.y, shift, mask);
        float x02 = cluster_gather(sbase, c0.z, shift, mask);
        float x03 = cluster_gather(sbase, c0.w, shift, mask);
        float x10 = cluster_gather(sbase, c1.x, shift, mask);
        float x11 = cluster_gather(sbase, c1.y, shift, mask);
        float x12 = cluster_gather(sbase, c1.z, shift, mask);
        float x13 = cluster_gather(sbase, c1.w, shift, mask);
        float x20 = cluster_gather(sbase, c2.x, shift, mask);
        float x21 = cluster_gather(sbase, c2.y, shift, mask);
        float x22 = cluster_gather(sbase, c2.z, shift, mask);
        float x23 = cluster_gather(sbase, c2.w, shift, mask);
        float x30 = cluster_gather(sbase, c3.x, shift, mask);
        float x31 = cluster_gather(sbase, c3.y, shift, mask);
        float x32 = cluster_gather(sbase, c3.z, shift, mask);
        float x33 = cluster_gather(sbase, c3.w, shift, mask);

        float w00 = __ldg(&Param_W[p0.x]), w01 = __ldg(&Param_W[p0.y]);
        float w02 = __ldg(&Param_W[p0.z]), w03 = __ldg(&Param_W[p0.w]);
        float w10 = __ldg(&Param_W[p1.x]), w11 = __ldg(&Param_W[p1.y]);
        float w12 = __ldg(&Param_W[p1.z]), w13 = __ldg(&Param_W[p1.w]);
        float w20 = __ldg(&Param_W[p2.x]), w21 = __ldg(&Param_W[p2.y]);
        float w22 = __ldg(&Param_W[p2.z]), w23 = __ldg(&Param_W[p2.w]);
        float w30 = __ldg(&Param_W[p3.x]), w31 = __ldg(&Param_W[p3.y]);
        float w32 = __ldg(&Param_W[p3.z]), w33 = __ldg(&Param_W[p3.w]);

        atomicAdd(&out[r0.x], w00 * x00);
        atomicAdd(&out[r0.y], w01 * x01);
        atomicAdd(&out[r0.z], w02 * x02);
        atomicAdd(&out[r0.w], w03 * x03);
        atomicAdd(&out[r1.x], w10 * x10);
        atomicAdd(&out[r1.y], w11 * x11);
        atomicAdd(&out[r1.z], w12 * x12);
        atomicAdd(&out[r1.w], w13 * x13);
        atomicAdd(&out[r2.x], w20 * x20);
        atomicAdd(&out[r2.y], w21 * x21);
        atomicAdd(&out[r2.z], w22 * x22);
        atomicAdd(&out[r2.w], w23 * x23);
        atomicAdd(&out[r3.x], w30 * x30);
        atomicAdd(&out[r3.y], w31 * x31);
        atomicAdd(&out[r3.z], w32 * x32);
        atomicAdd(&out[r3.w], w33 * x33);
    }
    // ---- remainder ----
    for (; i < e4; i += stride) {
        int4 r = __ldcs(&w_rows4[i]);
        int4 c = __ldcs(&w_cols4[i]);
        int4 p = __ldcs(&w_params4[i]);
        float xv0 = cluster_gather(sbase, c.x, shift, mask);
        float xv1 = cluster_gather(sbase, c.y, shift, mask);
        float xv2 = cluster_gather(sbase, c.z, shift, mask);
        float xv3 = cluster_gather(sbase, c.w, shift, mask);
        float w0 = __ldg(&Param_W[p.x]), w1 = __ldg(&Param_W[p.y]);
        float w2 = __ldg(&Param_W[p.z]), w3 = __ldg(&Param_W[p.w]);
        atomicAdd(&out[r.x], w0 * xv0);
        atomicAdd(&out[r.y], w1 * xv1);
        atomicAdd(&out[r.z], w2 * xv2);
        atomicAdd(&out[r.w], w3 * xv3);
    }

    // no CTA may exit while peers can still read its smem slice
    asm volatile("barrier.cluster.arrive.aligned;" ::: "memory");
    asm volatile("barrier.cluster.wait.aligned;" ::: "memory");
}

// ---------------- fallback flat kernel (R2 structure) ----------------
__global__ void __launch_bounds__(256) edge_scatter_flat(
        const float* __restrict__ x,
        const float* __restrict__ Param_W,
        const int4* __restrict__ w_rows4,
        const int4* __restrict__ w_cols4,
        const int4* __restrict__ w_params4,
        float* __restrict__ out, int e4) {
    int i = blockIdx.x * blockDim.x + threadIdx.x;
    if (i >= e4) return;
    int4 r = __ldcs(&w_rows4[i]);
    int4 c = __ldcs(&w_cols4[i]);
    int4 p = __ldcs(&w_params4[i]);
    float x0 = __ldg(&x[c.x]);
    float x1 = __ldg(&x[c.y]);
    float x2 = __ldg(&x[c.z]);
    float x3 = __ldg(&x[c.w]);
    float w0 = __ldg(&Param_W[p.x]);
    float w1 = __ldg(&Param_W[p.y]);
    float w2 = __ldg(&Param_W[p.z]);
    float w3 = __ldg(&Param_W[p.w]);
    atomicAdd(&out[r.x], w0 * x0);
    atomicAdd(&out[r.y], w1 * x1);
    atomicAdd(&out[r.z], w2 * x2);
    atomicAdd(&out[r.w], w3 * x3);
}

__global__ void edge_scatter_tail_kernel(const float* __restrict__ x,
                                         const float* __restrict__ Param_W,
                                         const int* __restrict__ w_rows,
                                         const int* __restrict__ w_cols,
                                         const int* __restrict__ w_params,
                                         float* __restrict__ out,
                                         int start, int e) {
    int i = start + blockIdx.x * blockDim.x + threadIdx.x;
    if (i < e) {
        atomicAdd(&out[w_rows[i]], __ldg(&Param_W[w_params[i]]) * __ldg(&x[w_cols[i]]));
    }
}

extern "C" void kernel_launch(void* const* d_in, const int* in_sizes, int n_in,
                              void* d_out, int out_size) {
    // metadata order: x, Param_W, Param_b, w_rows, w_cols, w_params, b_params
    const float* x        = (const float*)d_in[0];
    const float* Param_W  = (const float*)d_in[1];
    const float* Param_b  = (const float*)d_in[2];
    const int*   w_rows   = (const int*)d_in[3];
    const int*   w_cols   = (const int*)d_in[4];
    const int*   w_params = (const int*)d_in[5];
    const int*   b_params = (const int*)d_in[6];
    float* out = (float*)d_out;

    int n = out_size;          // N = 262144
    int e = in_sizes[3];       // E = 16777216
    int nx = in_sizes[0];      // == N

    // 1) bias init
    int n4 = n / 4;
    if (n4 > 0) {
        int threads = 256;
        int blocks = (n4 + threads - 1) / threads;
        bias_init_kernel<<<blocks, threads>>>(Param_b, (const int4*)b_params,
                                              (float4*)out, n4);
    }
    if (n4 * 4 < n) {
        int rem = n - n4 * 4;
        bias_init_tail_kernel<<<(rem + 255) / 256, 256>>>(Param_b, b_params, out,
                                                          n4 * 4, n);
    }

    // 2) edge scatter
    int e4 = e / 4;

    // cluster path requires nx divisible by CLUSTER_N with power-of-two slice
    int slice = nx / CLUSTER_N;
    bool pow2 = slice > 0 && (slice & (slice - 1)) == 0;
    bool cluster_ok = (nx % CLUSTER_N == 0) && pow2 &&
                      ((size_t)slice * sizeof(float) <= 160 * 1024);

    if (e4 > 0 && cluster_ok) {
        int shift = 0;
        while ((1 << shift) < slice) shift++;
        int mask = slice - 1;
        size_t smem = (size_t)slice * sizeof(float);

        static bool attr_done = false;
        if (!attr_done) {
            cudaFuncSetAttribute(edge_scatter_cluster,
                                 cudaFuncAttributeMaxDynamicSharedMemorySize,
                                 (int)smem);
            attr_done = true;
        }

        cudaLaunchConfig_t cfg = {};
        cfg.gridDim = {NUM_CLUSTERS * CLUSTER_N, 1, 1};
        cfg.blockDim = {CLUSTER_THREADS, 1, 1};
        cfg.dynamicSmemBytes = smem;
        cfg.stream = 0;
        cudaLaunchAttribute attrs[1];
        attrs[0].id = cudaLaunchAttributeClusterDimension;
        attrs[0].val.clusterDim = {CLUSTER_N, 1, 1};
        cfg.attrs = attrs;
        cfg.numAttrs = 1;

        cudaLaunchKernelEx(&cfg, edge_scatter_cluster,
                           x, Param_W,
                           (const int4*)w_rows, (const int4*)w_cols,
                           (const int4*)w_params,
                           out, e4, slice, shift, mask);
    } else if (e4 > 0) {
        int threads = 256;
        int blocks = (e4 + threads - 1) / threads;
        edge_scatter_flat<<<blocks, threads>>>(
            x, Param_W,
            (const int4*)w_rows, (const int4*)w_cols, (const int4*)w_params,
            out, e4);
    }

    int tail_start = e4 * 4;
    if (tail_start < e) {
        int rem = e - tail_start;
        edge_scatter_tail_kernel<<<(rem + 255) / 256, 256>>>(
            x, Param_W, w_rows, w_cols, w_params, out, tail_start, e);
    }
}

// round 14
// speedup vs baseline: 3.0600x; 3.0600x over previous
#include <cuda_runtime.h>
#include <stdint.h>

// Fused kernel. out must be zeroed beforehand (memset node).
// Blocks [0, bias_blocks): bias scatter  out[i] += Param_b[b_params[i]]
// Blocks [bias_blocks, ..): edge scatter out[r] += Param_W[p] * x[c]
// All contributions are atomic adds into a zeroed buffer -> order-free.
__global__ void __launch_bounds__(256) fused_scatter_kernel(
        const float* __restrict__ x,
        const float* __restrict__ Param_W,
        const int4* __restrict__ w_rows4,
        const int4* __restrict__ w_cols4,
        const int4* __restrict__ w_params4,
        const float* __restrict__ Param_b,
        const int4* __restrict__ b_params4,
        float* __restrict__ out,
        int e4, int n4, int bias_blocks) {
    if ((int)blockIdx.x < bias_blocks) {
        // ---- bias part: 4 outputs per thread ----
        int i = blockIdx.x * blockDim.x + threadIdx.x;
        if (i < n4) {
            int4 b = __ldcs(&b_params4[i]);
            float v0 = __ldg(&Param_b[b.x]);
            float v1 = __ldg(&Param_b[b.y]);
            float v2 = __ldg(&Param_b[b.z]);
            float v3 = __ldg(&Param_b[b.w]);
            int o = i * 4;
            atomicAdd(&out[o + 0], v0);
            atomicAdd(&out[o + 1], v1);
            atomicAdd(&out[o + 2], v2);
            atomicAdd(&out[o + 3], v3);
        }
        return;
    }

    // ---- edge part: champion R2 structure, 4 edges per thread ----
    int i = (blockIdx.x - bias_blocks) * blockDim.x + threadIdx.x;
    if (i >= e4) return;

    int4 r = __ldcs(&w_rows4[i]);
    int4 c = __ldcs(&w_cols4[i]);
    int4 p = __ldcs(&w_params4[i]);

    // Gathers first (maximize MLP before the dependent atomics)
    float x0 = __ldg(&x[c.x]);
    float x1 = __ldg(&x[c.y]);
    float x2 = __ldg(&x[c.z]);
    float x3 = __ldg(&x[c.w]);
    float w0 = __ldg(&Param_W[p.x]);
    float w1 = __ldg(&Param_W[p.y]);
    float w2 = __ldg(&Param_W[p.z]);
    float w3 = __ldg(&Param_W[p.w]);

    atomicAdd(&out[r.x], w0 * x0);
    atomicAdd(&out[r.y], w1 * x1);
    atomicAdd(&out[r.z], w2 * x2);
    atomicAdd(&out[r.w], w3 * x3);
}

// Scalar tails (not expected for this shape; kept for safety)
__global__ void bias_tail_kernel(const float* __restrict__ Param_b,
                                 const int* __restrict__ b_params,
                                 float* __restrict__ out, int start, int n) {
    int i = start + blockIdx.x * blockDim.x + threadIdx.x;
    if (i < n) atomicAdd(&out[i], Param_b[b_params[i]]);
}

__global__ void edge_tail_kernel(const float* __restrict__ x,
                                 const float* __restrict__ Param_W,
                                 const int* __restrict__ w_rows,
                                 const int* __restrict__ w_cols,
                                 const int* __restrict__ w_params,
                                 float* __restrict__ out,
                                 int start, int e) {
    int i = start + blockIdx.x * blockDim.x + threadIdx.x;
    if (i < e) {
        atomicAdd(&out[w_rows[i]], __ldg(&Param_W[w_params[i]]) * __ldg(&x[w_cols[i]]));
    }
}

extern "C" void kernel_launch(void* const* d_in, const int* in_sizes, int n_in,
                              void* d_out, int out_size) {
    // metadata order: x, Param_W, Param_b, w_rows, w_cols, w_params, b_params
    const float* x        = (const float*)d_in[0];
    const float* Param_W  = (const float*)d_in[1];
    const float* Param_b  = (const float*)d_in[2];
    const int*   w_rows   = (const int*)d_in[3];
    const int*   w_cols   = (const int*)d_in[4];
    const int*   w_params = (const int*)d_in[5];
    const int*   b_params = (const int*)d_in[6];
    float* out = (float*)d_out;

    int n = out_size;          // N = 262144
    int e = in_sizes[3];       // E = 16777216

    // 1) zero out (graph memset node — all later contributions are atomic adds)
    cudaMemsetAsync(out, 0, (size_t)n * sizeof(float), 0);

    // 2) fused bias + edge scatter
    int threads = 256;
    int n4 = n / 4;
    int e4 = e / 4;
    int bias_blocks = (n4 + threads - 1) / threads;   // 256 for N=262144
    int edge_blocks = (e4 + threads - 1) / threads;   // 16384
    int blocks = bias_blocks + edge_blocks;
    if (blocks > 0) {
        fused_scatter_kernel<<<blocks, threads>>>(
            x, Param_W,
            (const int4*)w_rows, (const int4*)w_cols, (const int4*)w_params,
            Param_b, (const int4*)b_params,
            out, e4, n4, bias_blocks);
    }

    // tails (no-ops for this shape)
    if (n4 * 4 < n) {
        int rem = n - n4 * 4;
        bias_tail_kernel<<<(rem + 255) / 256, 256>>>(Param_b, b_params, out,
                                                     n4 * 4, n);
    }
    int tail_start = e4 * 4;
    if (tail_start < e) {
        int rem = e - tail_start;
        edge_tail_kernel<<<(rem + 255) / 256, 256>>>(
            x, Param_W, w_rows, w_cols, w_params, out, tail_start, e);
    }
}